// round 7
// baseline (speedup 1.0000x reference)
#include <cuda_runtime.h>
#include <cuda_bf16.h>
#include <cstdint>
#include <math.h>

// Problem constants
#define B_    8192
#define C_    512
#define F_    8
#define COUP_ 1024
#define NBL_  2
#define D1_   256
#define D2_   256

// ---------------------------------------------------------------------------
// Scratch (device globals — no allocations allowed)
// ---------------------------------------------------------------------------
__device__ float g_X0[B_ * C_];
__device__ float g_X1[B_ * C_];
__device__ float g_Abuf[B_ * C_];
__device__ float g_LD[B_];
__device__ float g_scale[F_ * C_];
__device__ float g_lssum[F_];

// split-bf16 weight planes
__device__ __nv_bfloat16 g_Wph[F_ * C_ * C_],              g_Wpl[F_ * C_ * C_];
__device__ __nv_bfloat16 g_w0h[F_ * COUP_ * D1_],          g_w0l[F_ * COUP_ * D1_];
__device__ __nv_bfloat16 g_whh[F_ * NBL_ * COUP_ * COUP_], g_whl[F_ * NBL_ * COUP_ * COUP_];
__device__ __nv_bfloat16 g_woh[F_ * 2 * D2_ * COUP_],      g_wol[F_ * 2 * D2_ * COUP_];

// split-bf16 activation planes
__device__ __nv_bfloat16 g_XFh[B_ * C_],    g_XFl[B_ * C_];     // (x*scale+off) split
__device__ __nv_bfloat16 g_XAh[B_ * D1_],   g_XAl[B_ * D1_];    // x1 split
__device__ __nv_bfloat16 g_HAh[B_ * COUP_], g_HAl[B_ * COUP_];
__device__ __nv_bfloat16 g_HBh[B_ * COUP_], g_HBl[B_ * COUP_];

// ---------------------------------------------------------------------------
// Helpers
// ---------------------------------------------------------------------------
__device__ __forceinline__ uint32_t smem_u32(const void* p) {
    uint32_t a;
    asm("{ .reg .u64 t; cvta.to.shared.u64 t, %1; cvt.u32.u64 %0, t; }" : "=r"(a) : "l"(p));
    return a;
}
__device__ __forceinline__ void cpasync16(uint32_t s, const void* g) {
    asm volatile("cp.async.cg.shared.global [%0], [%1], 16;" :: "r"(s), "l"(g) : "memory");
}
__device__ __forceinline__ void cp_commit() { asm volatile("cp.async.commit_group;" ::: "memory"); }
__device__ __forceinline__ void cp_wait0()  { asm volatile("cp.async.wait_group 0;" ::: "memory"); }
__device__ __forceinline__ void cp_wait1()  { asm volatile("cp.async.wait_group 1;" ::: "memory"); }
__device__ __forceinline__ void cp_wait2()  { asm volatile("cp.async.wait_group 2;" ::: "memory"); }
__device__ __forceinline__ void ldsm4(uint32_t* r, uint32_t addr) {
    asm volatile("ldmatrix.sync.aligned.m8n8.x4.shared.b16 {%0,%1,%2,%3}, [%4];"
                 : "=r"(r[0]), "=r"(r[1]), "=r"(r[2]), "=r"(r[3]) : "r"(addr));
}
__device__ __forceinline__ void mma16816(float* d, const uint32_t* a, const uint32_t* b) {
    asm volatile("mma.sync.aligned.m16n8k16.row.col.f32.bf16.bf16.f32 "
                 "{%0,%1,%2,%3}, {%4,%5,%6,%7}, {%8,%9}, {%0,%1,%2,%3};"
                 : "+f"(d[0]), "+f"(d[1]), "+f"(d[2]), "+f"(d[3])
                 : "r"(a[0]), "r"(a[1]), "r"(a[2]), "r"(a[3]), "r"(b[0]), "r"(b[1]));
}
__device__ __forceinline__ uint32_t pk2(__nv_bfloat16 a, __nv_bfloat16 b) {
    return (uint32_t)__bfloat16_as_ushort(a) | ((uint32_t)__bfloat16_as_ushort(b) << 16);
}

// smem tile layout: 128 rows x 32 bf16 (64B/row), 16B chunk swizzle: c^((r>>1)&3)
#define TILE_BYTES 8192
#define STAGE_BYTES 32768           // A_hi, A_lo, B_hi, B_lo
#define NSTAGE 4
#define SM_BIAS_OFF (NSTAGE * STAGE_BYTES)      // 131072
#define SM_TOTAL (SM_BIAS_OFF + 512)

// ---------------------------------------------------------------------------
// Split-bf16 GEMM via mma.sync (HMMA):
//   Y[M=8192, N] = act(alpha * (A @ B^T + bias))
//   tile 128x128x32, 256 threads, warp grid 4(m) x 2(n), warp tile 32x64
//   4-stage cp.async pipeline, 1 __syncthreads per 32-K chunk
// ---------------------------------------------------------------------------
template <int OUT_F32, int OUT_SPLIT, int RELU>
__global__ __launch_bounds__(256)
void mma_gemm(const __nv_bfloat16* __restrict__ Ah, const __nv_bfloat16* __restrict__ Al,
              const __nv_bfloat16* __restrict__ Bh, const __nv_bfloat16* __restrict__ Bl,
              const float* __restrict__ bias,
              float* __restrict__ Yf, int ldy,
              __nv_bfloat16* __restrict__ Oh, __nv_bfloat16* __restrict__ Ol,
              int ldo, int split_w,
              int K, float alpha) {
    extern __shared__ char smem[];
    const uint32_t sb = smem_u32(smem);
    const int tid  = threadIdx.x;
    const int lane = tid & 31;
    const int wid  = tid >> 5;
    const int warp_m = wid & 3;
    const int warp_n = wid >> 2;
    const int m0 = blockIdx.y * 128;
    const int n0 = blockIdx.x * 128;

    float* bias_s = (float*)(smem + SM_BIAS_OFF);
    for (int j = tid; j < 128; j += 256) bias_s[j] = bias ? bias[n0 + j] : 0.0f;

    float acc[2][8][4];
#pragma unroll
    for (int mt = 0; mt < 2; mt++)
#pragma unroll
        for (int nt = 0; nt < 8; nt++)
#pragma unroll
            for (int q = 0; q < 4; q++) acc[mt][nt][q] = 0.0f;

    const int nchunks = K >> 5;

    auto prefetch = [&](int st, int kb) {
        uint32_t base = sb + st * STAGE_BYTES;
#pragma unroll
        for (int i = 0; i < 2; i++) {
            int v = tid + i * 256;            // 0..511
            int r = v >> 2, c = v & 3;
            uint32_t sw = (uint32_t)((c ^ ((r >> 1) & 3)) << 4) + r * 64;
            size_t ga = (size_t)(m0 + r) * K + kb + c * 8;
            size_t gb = (size_t)(n0 + r) * K + kb + c * 8;
            cpasync16(base + sw,                  Ah + ga);
            cpasync16(base + TILE_BYTES + sw,     Al + ga);
            cpasync16(base + 2 * TILE_BYTES + sw, Bh + gb);
            cpasync16(base + 3 * TILE_BYTES + sw, Bl + gb);
        }
        cp_commit();
    };

    auto compute = [&](int st) {
        uint32_t base = sb + st * STAGE_BYTES;
#pragma unroll
        for (int ks = 0; ks < 2; ks++) {
            uint32_t ah[2][4], al_[2][4];
#pragma unroll
            for (int mt = 0; mt < 2; mt++) {
                int gq  = lane >> 3;
                int row = warp_m * 32 + mt * 16 + (lane & 7) + (gq & 1) * 8;
                int ch  = ks * 2 + (gq >> 1);
                uint32_t o = row * 64 + ((ch ^ ((row >> 1) & 3)) << 4);
                ldsm4(ah[mt],  base + o);
                ldsm4(al_[mt], base + TILE_BYTES + o);
            }
            uint32_t bh_[4][4], bl_[4][4];
#pragma unroll
            for (int nt = 0; nt < 4; nt++) {
                int row = warp_n * 64 + nt * 16 + (lane & 7) + ((lane >> 4) & 1) * 8;
                int ch  = ks * 2 + ((lane >> 3) & 1);
                uint32_t o = row * 64 + ((ch ^ ((row >> 1) & 3)) << 4);
                ldsm4(bh_[nt], base + 2 * TILE_BYTES + o);
                ldsm4(bl_[nt], base + 3 * TILE_BYTES + o);
            }
#pragma unroll
            for (int mt = 0; mt < 2; mt++)
#pragma unroll
                for (int nt = 0; nt < 4; nt++)
#pragma unroll
                    for (int hf = 0; hf < 2; hf++) {
                        float* d = acc[mt][nt * 2 + hf];
                        mma16816(d, ah[mt],  &bh_[nt][hf * 2]);
                        mma16816(d, ah[mt],  &bl_[nt][hf * 2]);
                        mma16816(d, al_[mt], &bh_[nt][hf * 2]);
                    }
        }
    };

    // 4-stage pipeline: prologue fills 3 stages, 1 sync per chunk
    prefetch(0, 0);
    prefetch(1, 32);
    prefetch(2, 64);
    for (int kc = 0; kc < nchunks; kc++) {
        if (kc <= nchunks - 3)      cp_wait2();
        else if (kc == nchunks - 2) cp_wait1();
        else                        cp_wait0();
        __syncthreads();
        if (kc + 3 < nchunks) prefetch((kc + 3) & 3, (kc + 3) * 32);
        compute(kc & 3);
    }

    // ---- epilogue --------------------------------------------------------
    const int qr  = lane >> 2;
    const int qc2 = (lane & 3) * 2;
#pragma unroll
    for (int mt = 0; mt < 2; mt++) {
        int r0 = m0 + warp_m * 32 + mt * 16 + qr;
        int r1 = r0 + 8;
#pragma unroll
        for (int nt = 0; nt < 8; nt++) {
            float* d = acc[mt][nt];
            int col_l = warp_n * 64 + nt * 8 + qc2;
            int col_g = n0 + col_l;
            float bb0 = bias_s[col_l], bb1 = bias_s[col_l + 1];
            float v00 = (d[0] + bb0) * alpha;
            float v01 = (d[1] + bb1) * alpha;
            float v10 = (d[2] + bb0) * alpha;
            float v11 = (d[3] + bb1) * alpha;
            if (RELU) {
                v00 = fmaxf(v00, 0.0f); v01 = fmaxf(v01, 0.0f);
                v10 = fmaxf(v10, 0.0f); v11 = fmaxf(v11, 0.0f);
            }
            if (OUT_F32) {
                *(float2*)(Yf + (size_t)r0 * ldy + col_g) = make_float2(v00, v01);
                *(float2*)(Yf + (size_t)r1 * ldy + col_g) = make_float2(v10, v11);
            }
            if (OUT_SPLIT && col_g < split_w) {
                __nv_bfloat16 h00 = __float2bfloat16(v00), h01 = __float2bfloat16(v01);
                __nv_bfloat16 h10 = __float2bfloat16(v10), h11 = __float2bfloat16(v11);
                __nv_bfloat16 l00 = __float2bfloat16(v00 - __bfloat162float(h00));
                __nv_bfloat16 l01 = __float2bfloat16(v01 - __bfloat162float(h01));
                __nv_bfloat16 l10 = __float2bfloat16(v10 - __bfloat162float(h10));
                __nv_bfloat16 l11 = __float2bfloat16(v11 - __bfloat162float(h11));
                *(uint32_t*)(Oh + (size_t)r0 * ldo + col_g) = pk2(h00, h01);
                *(uint32_t*)(Oh + (size_t)r1 * ldo + col_g) = pk2(h10, h11);
                *(uint32_t*)(Ol + (size_t)r0 * ldo + col_g) = pk2(l00, l01);
                *(uint32_t*)(Ol + (size_t)r1 * ldo + col_g) = pk2(l10, l11);
            }
        }
    }
}

// ---------------------------------------------------------------------------
// Weight fp32 -> split bf16
// ---------------------------------------------------------------------------
__global__ void split_kernel(const float* __restrict__ src,
                             __nv_bfloat16* __restrict__ hi,
                             __nv_bfloat16* __restrict__ lo, int n) {
    int i = blockIdx.x * blockDim.x + threadIdx.x;
    if (i < n) {
        float v = src[i];
        __nv_bfloat16 h = __float2bfloat16(v);
        hi[i] = h;
        lo[i] = __float2bfloat16(v - __bfloat162float(h));
    }
}

__global__ void prep_scale_kernel(const float* __restrict__ g) {
    int f = blockIdx.x;
    int c = threadIdx.x;
    float gv = g[f * C_ + c];
    float sc = 0.2f * log1pf(expf(0.5f * gv));
    g_scale[f * C_ + c] = sc;
    __shared__ float red[C_];
    red[c] = logf(sc);
    __syncthreads();
    for (int s = C_ / 2; s > 0; s >>= 1) {
        if (c < s) red[c] += red[c + s];
        __syncthreads();
    }
    if (c == 0) g_lssum[f] = red[0];
}

// flow-0 input prep: XF = split(z0 * scale0 + off0)
__global__ void prep0_kernel(const float* __restrict__ z0) {
    int i = blockIdx.x * blockDim.x + threadIdx.x;
    if (i < B_ * C_) {
        int c = i & (C_ - 1);
        float v = fmaf(z0[i], g_scale[c], 0.0f);
        // off is flow 0's off — passed via g? use global scale only; off added below
        // (filled in launch via separate pointer-free path: see coupling for f>0)
        v = v; // placeholder, replaced below
    }
}

// actual prep0 with off pointer
__global__ void prep0_full_kernel(const float* __restrict__ z0,
                                  const float* __restrict__ off0) {
    int i = blockIdx.x * blockDim.x + threadIdx.x;
    if (i < B_ * C_) {
        int c = i & (C_ - 1);
        float v = fmaf(z0[i], g_scale[c], off0[c]);
        __nv_bfloat16 h = __float2bfloat16(v);
        g_XFh[i] = h;
        g_XFl[i] = __float2bfloat16(v - __bfloat162float(h));
    }
}

// ---------------------------------------------------------------------------
// Coupling + next-flow input prep:
//   s = 2*tanh(a[:, :256]); t = a[:, 256:]
//   x2' = x2*exp(s) + t ;  LD (+)= rowsum(s) + lssum[f]
//   if do_next: XF = split(x * scale_next + off_next)  (full 512 cols)
// 8 warps per block, one row per warp. grid = B/8.
// ---------------------------------------------------------------------------
__global__ __launch_bounds__(256)
void coupling_kernel(float* __restrict__ X, int f,
                     const float* __restrict__ scale_next,
                     const float* __restrict__ off_next,
                     int do_next) {
    int warp = threadIdx.x >> 5;
    int lane = threadIdx.x & 31;
    int row  = blockIdx.x * 8 + warp;
    const float* arow = g_Abuf + (size_t)row * C_;
    float*       xrow = X + (size_t)row * C_;
    __nv_bfloat16* fh = g_XFh + (size_t)row * C_;
    __nv_bfloat16* fl = g_XFl + (size_t)row * C_;

    float sum = 0.0f;
#pragma unroll
    for (int it = 0; it < 8; it++) {
        int c = lane + it * 32;                    // 0..255
        float s  = 2.0f * tanhf(arow[c]);
        float t  = arow[D1_ + c];
        float x2 = xrow[D1_ + c] * expf(s) + t;
        xrow[D1_ + c] = x2;
        sum += s;
        if (do_next) {
            float x1v = xrow[c];
            float v1 = fmaf(x1v, scale_next[c],        off_next[c]);
            float v2 = fmaf(x2,  scale_next[D1_ + c],  off_next[D1_ + c]);
            __nv_bfloat16 h1 = __float2bfloat16(v1);
            __nv_bfloat16 h2 = __float2bfloat16(v2);
            fh[c]        = h1;
            fh[D1_ + c]  = h2;
            fl[c]        = __float2bfloat16(v1 - __bfloat162float(h1));
            fl[D1_ + c]  = __float2bfloat16(v2 - __bfloat162float(h2));
        }
    }
#pragma unroll
    for (int o = 16; o > 0; o >>= 1)
        sum += __shfl_down_sync(0xFFFFFFFFu, sum, o);
    if (lane == 0) {
        float prev = (f == 0) ? 0.0f : g_LD[row];
        g_LD[row] = prev + sum + g_lssum[f];
    }
}

__global__ void finalize_kernel(const float* __restrict__ X, float* __restrict__ out) {
    int i = blockIdx.x * blockDim.x + threadIdx.x;
    if (i < B_ * C_) out[i] = X[i];
    else if (i < B_ * C_ + B_) out[i] = g_LD[i - B_ * C_];
}

// ---------------------------------------------------------------------------
extern "C" void kernel_launch(void* const* d_in, const int* in_sizes, int n_in,
                              void* d_out, int out_size) {
    const float* z0  = (const float*)d_in[0];
    const float* Wp  = (const float*)d_in[1];
    const float* g   = (const float*)d_in[2];
    const float* off = (const float*)d_in[3];
    const float* w0  = (const float*)d_in[4];
    const float* b0  = (const float*)d_in[5];
    const float* wh  = (const float*)d_in[6];
    const float* bh  = (const float*)d_in[7];
    const float* wo  = (const float*)d_in[8];
    const float* bo  = (const float*)d_in[9];
    float* out = (float*)d_out;

    float *X0, *X1, *Abuf, *scaleP;
    __nv_bfloat16 *Wph, *Wpl, *w0h, *w0l, *whh, *whl, *woh, *wol;
    __nv_bfloat16 *XFh, *XFl, *XAh, *XAl, *HAh, *HAl, *HBh, *HBl;
    cudaGetSymbolAddress((void**)&X0, g_X0);
    cudaGetSymbolAddress((void**)&X1, g_X1);
    cudaGetSymbolAddress((void**)&Abuf, g_Abuf);
    cudaGetSymbolAddress((void**)&scaleP, g_scale);
    cudaGetSymbolAddress((void**)&Wph, g_Wph); cudaGetSymbolAddress((void**)&Wpl, g_Wpl);
    cudaGetSymbolAddress((void**)&w0h, g_w0h); cudaGetSymbolAddress((void**)&w0l, g_w0l);
    cudaGetSymbolAddress((void**)&whh, g_whh); cudaGetSymbolAddress((void**)&whl, g_whl);
    cudaGetSymbolAddress((void**)&woh, g_woh); cudaGetSymbolAddress((void**)&wol, g_wol);
    cudaGetSymbolAddress((void**)&XFh, g_XFh); cudaGetSymbolAddress((void**)&XFl, g_XFl);
    cudaGetSymbolAddress((void**)&XAh, g_XAh); cudaGetSymbolAddress((void**)&XAl, g_XAl);
    cudaGetSymbolAddress((void**)&HAh, g_HAh); cudaGetSymbolAddress((void**)&HAl, g_HAl);
    cudaGetSymbolAddress((void**)&HBh, g_HBh); cudaGetSymbolAddress((void**)&HBl, g_HBl);

    cudaFuncSetAttribute(mma_gemm<1,1,0>, cudaFuncAttributeMaxDynamicSharedMemorySize, SM_TOTAL);
    cudaFuncSetAttribute(mma_gemm<0,1,1>, cudaFuncAttributeMaxDynamicSharedMemorySize, SM_TOTAL);
    cudaFuncSetAttribute(mma_gemm<1,0,0>, cudaFuncAttributeMaxDynamicSharedMemorySize, SM_TOTAL);

    prep_scale_kernel<<<F_, C_>>>(g);

    {
        int n;
        n = F_ * C_ * C_;              split_kernel<<<(n + 255) / 256, 256>>>(Wp, Wph, Wpl, n);
        n = F_ * COUP_ * D1_;          split_kernel<<<(n + 255) / 256, 256>>>(w0, w0h, w0l, n);
        n = F_ * NBL_ * COUP_ * COUP_; split_kernel<<<(n + 255) / 256, 256>>>(wh, whh, whl, n);
        n = F_ * 2 * D2_ * COUP_;      split_kernel<<<(n + 255) / 256, 256>>>(wo, woh, wol, n);
    }

    // flow-0 input prep (uses g_scale[0:512] computed by prep_scale_kernel)
    prep0_full_kernel<<<(B_ * C_ + 255) / 256, 256>>>(z0, off);

    for (int f = 0; f < F_; f++) {
        float* Xcur = (f & 1) ? X1 : X0;

        const __nv_bfloat16* Wph_f = Wph + (size_t)f * C_ * C_;
        const __nv_bfloat16* Wpl_f = Wpl + (size_t)f * C_ * C_;
        const __nv_bfloat16* w0h_f = w0h + (size_t)f * COUP_ * D1_;
        const __nv_bfloat16* w0l_f = w0l + (size_t)f * COUP_ * D1_;
        const __nv_bfloat16* whh0  = whh + (size_t)f * NBL_ * COUP_ * COUP_;
        const __nv_bfloat16* whl0  = whl + (size_t)f * NBL_ * COUP_ * COUP_;
        const __nv_bfloat16* whh1  = whh0 + (size_t)COUP_ * COUP_;
        const __nv_bfloat16* whl1  = whl0 + (size_t)COUP_ * COUP_;
        const __nv_bfloat16* woh_f = woh + (size_t)f * 2 * D2_ * COUP_;
        const __nv_bfloat16* wol_f = wol + (size_t)f * 2 * D2_ * COUP_;
        const float* b0_f  = b0 + (size_t)f * COUP_;
        const float* bh_f0 = bh + (size_t)f * NBL_ * COUP_;
        const float* bh_f1 = bh_f0 + COUP_;
        const float* bo_f  = bo + (size_t)f * 2 * D2_;

        // 1) X = XF @ Wp^T ; fp32 out + x1 split planes
        mma_gemm<1,1,0><<<dim3(C_ / 128, B_ / 128), 256, SM_TOTAL>>>(
            XFh, XFl, Wph_f, Wpl_f, nullptr,
            Xcur, C_, XAh, XAl, D1_, D1_, C_, 1.0f);

        // 2) H = relu(x1 @ w0^T + b0)
        mma_gemm<0,1,1><<<dim3(COUP_ / 128, B_ / 128), 256, SM_TOTAL>>>(
            XAh, XAl, w0h_f, w0l_f, b0_f,
            nullptr, 0, HAh, HAl, COUP_, COUP_, D1_, 1.0f);

        // 3) H' = relu(H @ wh0^T + bh0)
        mma_gemm<0,1,1><<<dim3(COUP_ / 128, B_ / 128), 256, SM_TOTAL>>>(
            HAh, HAl, whh0, whl0, bh_f0,
            nullptr, 0, HBh, HBl, COUP_, COUP_, COUP_, 1.0f);

        // 4) H = relu(H' @ wh1^T + bh1)
        mma_gemm<0,1,1><<<dim3(COUP_ / 128, B_ / 128), 256, SM_TOTAL>>>(
            HBh, HBl, whh1, whl1, bh_f1,
            nullptr, 0, HAh, HAl, COUP_, COUP_, COUP_, 1.0f);

        // 5) a = 0.1*(H @ wo^T + bo) ; fp32 out
        mma_gemm<1,0,0><<<dim3((2 * D2_) / 128, B_ / 128), 256, SM_TOTAL>>>(
            HAh, HAl, woh_f, wol_f, bo_f,
            Abuf, C_, nullptr, nullptr, 0, 0, COUP_, 0.1f);

        // 6) coupling + log-det + next-flow input prep
        int do_next = (f + 1 < F_) ? 1 : 0;
        const float* sc_n  = scaleP + (size_t)((f + 1) % F_) * C_;
        const float* off_n = off + (size_t)((f + 1) % F_) * C_;
        coupling_kernel<<<B_ / 8, 256>>>(Xcur, f, sc_n, off_n, do_next);
    }

    finalize_kernel<<<(B_ * C_ + B_ + 255) / 256, 256>>>(X1, out);
}

// round 8
// speedup vs baseline: 1.1444x; 1.1444x over previous
#include <cuda_runtime.h>
#include <cuda_bf16.h>
#include <cstdint>
#include <math.h>

// Problem constants
#define B_    8192
#define C_    512
#define F_    8
#define COUP_ 1024
#define NBL_  2
#define D1_   256
#define D2_   256

// ---------------------------------------------------------------------------
// Scratch (device globals — no allocations allowed)
// ---------------------------------------------------------------------------
__device__ float g_X0[B_ * C_];
__device__ float g_X1[B_ * C_];
__device__ float g_Abuf[B_ * C_];
__device__ float g_LD[B_];
__device__ float g_scale[F_ * C_];
__device__ float g_lssum[F_];

// split-bf16 weight planes
__device__ __nv_bfloat16 g_Wph[F_ * C_ * C_],              g_Wpl[F_ * C_ * C_];
__device__ __nv_bfloat16 g_w0h[F_ * COUP_ * D1_],          g_w0l[F_ * COUP_ * D1_];
__device__ __nv_bfloat16 g_whh[F_ * NBL_ * COUP_ * COUP_], g_whl[F_ * NBL_ * COUP_ * COUP_];
__device__ __nv_bfloat16 g_woh[F_ * 2 * D2_ * COUP_],      g_wol[F_ * 2 * D2_ * COUP_];

// split-bf16 activation planes
__device__ __nv_bfloat16 g_XFh[B_ * C_],    g_XFl[B_ * C_];     // (x*scale+off) split
__device__ __nv_bfloat16 g_XAh[B_ * D1_],   g_XAl[B_ * D1_];    // x1 split
__device__ __nv_bfloat16 g_HAh[B_ * COUP_], g_HAl[B_ * COUP_];
__device__ __nv_bfloat16 g_HBh[B_ * COUP_], g_HBl[B_ * COUP_];

// ---------------------------------------------------------------------------
// Helpers
// ---------------------------------------------------------------------------
__device__ __forceinline__ uint32_t smem_u32(const void* p) {
    uint32_t a;
    asm("{ .reg .u64 t; cvta.to.shared.u64 t, %1; cvt.u32.u64 %0, t; }" : "=r"(a) : "l"(p));
    return a;
}
__device__ __forceinline__ void cpasync16(uint32_t s, const void* g) {
    asm volatile("cp.async.cg.shared.global [%0], [%1], 16;" :: "r"(s), "l"(g) : "memory");
}
__device__ __forceinline__ void cp_commit() { asm volatile("cp.async.commit_group;" ::: "memory"); }
__device__ __forceinline__ void cp_wait0()  { asm volatile("cp.async.wait_group 0;" ::: "memory"); }
__device__ __forceinline__ void cp_wait1()  { asm volatile("cp.async.wait_group 1;" ::: "memory"); }
__device__ __forceinline__ void ldsm4(uint32_t* r, uint32_t addr) {
    asm volatile("ldmatrix.sync.aligned.m8n8.x4.shared.b16 {%0,%1,%2,%3}, [%4];"
                 : "=r"(r[0]), "=r"(r[1]), "=r"(r[2]), "=r"(r[3]) : "r"(addr));
}
__device__ __forceinline__ void mma16816(float* d, const uint32_t* a, const uint32_t* b) {
    asm volatile("mma.sync.aligned.m16n8k16.row.col.f32.bf16.bf16.f32 "
                 "{%0,%1,%2,%3}, {%4,%5,%6,%7}, {%8,%9}, {%0,%1,%2,%3};"
                 : "+f"(d[0]), "+f"(d[1]), "+f"(d[2]), "+f"(d[3])
                 : "r"(a[0]), "r"(a[1]), "r"(a[2]), "r"(a[3]), "r"(b[0]), "r"(b[1]));
}
__device__ __forceinline__ uint32_t pk2(__nv_bfloat16 a, __nv_bfloat16 b) {
    return (uint32_t)__bfloat16_as_ushort(a) | ((uint32_t)__bfloat16_as_ushort(b) << 16);
}

// smem tile layout: 128 rows x 32 bf16 (64B/row), 16B chunk swizzle: c^((r>>1)&3)
#define TILE_BYTES 8192
#define STAGE_BYTES 32768           // A_hi, A_lo, B_hi, B_lo
#define NSTAGE 3
#define SM_BIAS_OFF (NSTAGE * STAGE_BYTES)      // 98304
#define SM_TOTAL (SM_BIAS_OFF + 512)            // 98816 -> 2 CTAs/SM

// ---------------------------------------------------------------------------
// Split-bf16 GEMM via mma.sync (HMMA):
//   Y[M=8192, N] = act(alpha * (A @ B^T + bias))
//   tile 128x128x32, 256 threads, warp grid 4(m) x 2(n), warp tile 32x64
//   3-stage cp.async pipeline, 1 __syncthreads per 32-K chunk, 2 CTAs/SM
// ---------------------------------------------------------------------------
template <int OUT_F32, int OUT_SPLIT, int RELU>
__global__ __launch_bounds__(256)
void mma_gemm(const __nv_bfloat16* __restrict__ Ah, const __nv_bfloat16* __restrict__ Al,
              const __nv_bfloat16* __restrict__ Bh, const __nv_bfloat16* __restrict__ Bl,
              const float* __restrict__ bias,
              float* __restrict__ Yf, int ldy,
              __nv_bfloat16* __restrict__ Oh, __nv_bfloat16* __restrict__ Ol,
              int ldo, int split_w,
              int K, float alpha) {
    extern __shared__ char smem[];
    const uint32_t sb = smem_u32(smem);
    const int tid  = threadIdx.x;
    const int lane = tid & 31;
    const int wid  = tid >> 5;
    const int warp_m = wid & 3;
    const int warp_n = wid >> 2;
    const int m0 = blockIdx.y * 128;
    const int n0 = blockIdx.x * 128;

    float* bias_s = (float*)(smem + SM_BIAS_OFF);
    for (int j = tid; j < 128; j += 256) bias_s[j] = bias ? bias[n0 + j] : 0.0f;

    float acc[2][8][4];
#pragma unroll
    for (int mt = 0; mt < 2; mt++)
#pragma unroll
        for (int nt = 0; nt < 8; nt++)
#pragma unroll
            for (int q = 0; q < 4; q++) acc[mt][nt][q] = 0.0f;

    const int nchunks = K >> 5;

    auto prefetch = [&](int st, int kb) {
        uint32_t base = sb + st * STAGE_BYTES;
#pragma unroll
        for (int i = 0; i < 2; i++) {
            int v = tid + i * 256;            // 0..511
            int r = v >> 2, c = v & 3;
            uint32_t sw = (uint32_t)((c ^ ((r >> 1) & 3)) << 4) + r * 64;
            size_t ga = (size_t)(m0 + r) * K + kb + c * 8;
            size_t gb = (size_t)(n0 + r) * K + kb + c * 8;
            cpasync16(base + sw,                  Ah + ga);
            cpasync16(base + TILE_BYTES + sw,     Al + ga);
            cpasync16(base + 2 * TILE_BYTES + sw, Bh + gb);
            cpasync16(base + 3 * TILE_BYTES + sw, Bl + gb);
        }
        cp_commit();
    };

    auto compute = [&](int st) {
        uint32_t base = sb + st * STAGE_BYTES;
#pragma unroll
        for (int ks = 0; ks < 2; ks++) {
            uint32_t ah[2][4], al_[2][4];
#pragma unroll
            for (int mt = 0; mt < 2; mt++) {
                int gq  = lane >> 3;
                int row = warp_m * 32 + mt * 16 + (lane & 7) + (gq & 1) * 8;
                int ch  = ks * 2 + (gq >> 1);
                uint32_t o = row * 64 + ((ch ^ ((row >> 1) & 3)) << 4);
                ldsm4(ah[mt],  base + o);
                ldsm4(al_[mt], base + TILE_BYTES + o);
            }
            uint32_t bh_[4][4], bl_[4][4];
#pragma unroll
            for (int nt = 0; nt < 4; nt++) {
                int row = warp_n * 64 + nt * 16 + (lane & 7) + ((lane >> 4) & 1) * 8;
                int ch  = ks * 2 + ((lane >> 3) & 1);
                uint32_t o = row * 64 + ((ch ^ ((row >> 1) & 3)) << 4);
                ldsm4(bh_[nt], base + 2 * TILE_BYTES + o);
                ldsm4(bl_[nt], base + 3 * TILE_BYTES + o);
            }
#pragma unroll
            for (int mt = 0; mt < 2; mt++)
#pragma unroll
                for (int nt = 0; nt < 4; nt++)
#pragma unroll
                    for (int hf = 0; hf < 2; hf++) {
                        float* d = acc[mt][nt * 2 + hf];
                        mma16816(d, ah[mt],  &bh_[nt][hf * 2]);
                        mma16816(d, ah[mt],  &bl_[nt][hf * 2]);
                        mma16816(d, al_[mt], &bh_[nt][hf * 2]);
                    }
        }
    };

    // 3-stage pipeline: prologue fills 2 stages, 1 sync per chunk.
    // At iter kc: wait until group kc is done, sync (also protects stage
    // (kc-1)%3 — computed last iter — from the overwrite below), prefetch
    // kc+2 into stage (kc+2)%3, compute kc.
    prefetch(0, 0);
    prefetch(1, 32);
    for (int kc = 0; kc < nchunks; kc++) {
        if (kc + 1 < nchunks) cp_wait1();
        else                  cp_wait0();
        __syncthreads();
        if (kc + 2 < nchunks) prefetch((kc + 2) % 3, (kc + 2) * 32);
        compute(kc % 3);
    }

    // ---- epilogue --------------------------------------------------------
    const int qr  = lane >> 2;
    const int qc2 = (lane & 3) * 2;
#pragma unroll
    for (int mt = 0; mt < 2; mt++) {
        int r0 = m0 + warp_m * 32 + mt * 16 + qr;
        int r1 = r0 + 8;
#pragma unroll
        for (int nt = 0; nt < 8; nt++) {
            float* d = acc[mt][nt];
            int col_l = warp_n * 64 + nt * 8 + qc2;
            int col_g = n0 + col_l;
            float bb0 = bias_s[col_l], bb1 = bias_s[col_l + 1];
            float v00 = (d[0] + bb0) * alpha;
            float v01 = (d[1] + bb1) * alpha;
            float v10 = (d[2] + bb0) * alpha;
            float v11 = (d[3] + bb1) * alpha;
            if (RELU) {
                v00 = fmaxf(v00, 0.0f); v01 = fmaxf(v01, 0.0f);
                v10 = fmaxf(v10, 0.0f); v11 = fmaxf(v11, 0.0f);
            }
            if (OUT_F32) {
                *(float2*)(Yf + (size_t)r0 * ldy + col_g) = make_float2(v00, v01);
                *(float2*)(Yf + (size_t)r1 * ldy + col_g) = make_float2(v10, v11);
            }
            if (OUT_SPLIT && col_g < split_w) {
                __nv_bfloat16 h00 = __float2bfloat16(v00), h01 = __float2bfloat16(v01);
                __nv_bfloat16 h10 = __float2bfloat16(v10), h11 = __float2bfloat16(v11);
                __nv_bfloat16 l00 = __float2bfloat16(v00 - __bfloat162float(h00));
                __nv_bfloat16 l01 = __float2bfloat16(v01 - __bfloat162float(h01));
                __nv_bfloat16 l10 = __float2bfloat16(v10 - __bfloat162float(h10));
                __nv_bfloat16 l11 = __float2bfloat16(v11 - __bfloat162float(h11));
                *(uint32_t*)(Oh + (size_t)r0 * ldo + col_g) = pk2(h00, h01);
                *(uint32_t*)(Oh + (size_t)r1 * ldo + col_g) = pk2(h10, h11);
                *(uint32_t*)(Ol + (size_t)r0 * ldo + col_g) = pk2(l00, l01);
                *(uint32_t*)(Ol + (size_t)r1 * ldo + col_g) = pk2(l10, l11);
            }
        }
    }
}

// ---------------------------------------------------------------------------
// Weight fp32 -> split bf16
// ---------------------------------------------------------------------------
__global__ void split_kernel(const float* __restrict__ src,
                             __nv_bfloat16* __restrict__ hi,
                             __nv_bfloat16* __restrict__ lo, int n) {
    int i = blockIdx.x * blockDim.x + threadIdx.x;
    if (i < n) {
        float v = src[i];
        __nv_bfloat16 h = __float2bfloat16(v);
        hi[i] = h;
        lo[i] = __float2bfloat16(v - __bfloat162float(h));
    }
}

__global__ void prep_scale_kernel(const float* __restrict__ g) {
    int f = blockIdx.x;
    int c = threadIdx.x;
    float gv = g[f * C_ + c];
    float sc = 0.2f * log1pf(expf(0.5f * gv));
    g_scale[f * C_ + c] = sc;
    __shared__ float red[C_];
    red[c] = logf(sc);
    __syncthreads();
    for (int s = C_ / 2; s > 0; s >>= 1) {
        if (c < s) red[c] += red[c + s];
        __syncthreads();
    }
    if (c == 0) g_lssum[f] = red[0];
}

// flow-0 input prep: XF = split(z0 * scale0 + off0)
__global__ void prep0_full_kernel(const float* __restrict__ z0,
                                  const float* __restrict__ off0) {
    int i = blockIdx.x * blockDim.x + threadIdx.x;
    if (i < B_ * C_) {
        int c = i & (C_ - 1);
        float v = fmaf(z0[i], g_scale[c], off0[c]);
        __nv_bfloat16 h = __float2bfloat16(v);
        g_XFh[i] = h;
        g_XFl[i] = __float2bfloat16(v - __bfloat162float(h));
    }
}

// ---------------------------------------------------------------------------
// Coupling + next-flow input prep
// ---------------------------------------------------------------------------
__global__ __launch_bounds__(256)
void coupling_kernel(float* __restrict__ X, int f,
                     const float* __restrict__ scale_next,
                     const float* __restrict__ off_next,
                     int do_next) {
    int warp = threadIdx.x >> 5;
    int lane = threadIdx.x & 31;
    int row  = blockIdx.x * 8 + warp;
    const float* arow = g_Abuf + (size_t)row * C_;
    float*       xrow = X + (size_t)row * C_;
    __nv_bfloat16* fh = g_XFh + (size_t)row * C_;
    __nv_bfloat16* fl = g_XFl + (size_t)row * C_;

    float sum = 0.0f;
#pragma unroll
    for (int it = 0; it < 8; it++) {
        int c = lane + it * 32;                    // 0..255
        float s  = 2.0f * tanhf(arow[c]);
        float t  = arow[D1_ + c];
        float x2 = xrow[D1_ + c] * expf(s) + t;
        xrow[D1_ + c] = x2;
        sum += s;
        if (do_next) {
            float x1v = xrow[c];
            float v1 = fmaf(x1v, scale_next[c],        off_next[c]);
            float v2 = fmaf(x2,  scale_next[D1_ + c],  off_next[D1_ + c]);
            __nv_bfloat16 h1 = __float2bfloat16(v1);
            __nv_bfloat16 h2 = __float2bfloat16(v2);
            fh[c]        = h1;
            fh[D1_ + c]  = h2;
            fl[c]        = __float2bfloat16(v1 - __bfloat162float(h1));
            fl[D1_ + c]  = __float2bfloat16(v2 - __bfloat162float(h2));
        }
    }
#pragma unroll
    for (int o = 16; o > 0; o >>= 1)
        sum += __shfl_down_sync(0xFFFFFFFFu, sum, o);
    if (lane == 0) {
        float prev = (f == 0) ? 0.0f : g_LD[row];
        g_LD[row] = prev + sum + g_lssum[f];
    }
}

__global__ void finalize_kernel(const float* __restrict__ X, float* __restrict__ out) {
    int i = blockIdx.x * blockDim.x + threadIdx.x;
    if (i < B_ * C_) out[i] = X[i];
    else if (i < B_ * C_ + B_) out[i] = g_LD[i - B_ * C_];
}

// ---------------------------------------------------------------------------
extern "C" void kernel_launch(void* const* d_in, const int* in_sizes, int n_in,
                              void* d_out, int out_size) {
    const float* z0  = (const float*)d_in[0];
    const float* Wp  = (const float*)d_in[1];
    const float* g   = (const float*)d_in[2];
    const float* off = (const float*)d_in[3];
    const float* w0  = (const float*)d_in[4];
    const float* b0  = (const float*)d_in[5];
    const float* wh  = (const float*)d_in[6];
    const float* bh  = (const float*)d_in[7];
    const float* wo  = (const float*)d_in[8];
    const float* bo  = (const float*)d_in[9];
    float* out = (float*)d_out;

    float *X0, *X1, *Abuf, *scaleP;
    __nv_bfloat16 *Wph, *Wpl, *w0h, *w0l, *whh, *whl, *woh, *wol;
    __nv_bfloat16 *XFh, *XFl, *XAh, *XAl, *HAh, *HAl, *HBh, *HBl;
    cudaGetSymbolAddress((void**)&X0, g_X0);
    cudaGetSymbolAddress((void**)&X1, g_X1);
    cudaGetSymbolAddress((void**)&Abuf, g_Abuf);
    cudaGetSymbolAddress((void**)&scaleP, g_scale);
    cudaGetSymbolAddress((void**)&Wph, g_Wph); cudaGetSymbolAddress((void**)&Wpl, g_Wpl);
    cudaGetSymbolAddress((void**)&w0h, g_w0h); cudaGetSymbolAddress((void**)&w0l, g_w0l);
    cudaGetSymbolAddress((void**)&whh, g_whh); cudaGetSymbolAddress((void**)&whl, g_whl);
    cudaGetSymbolAddress((void**)&woh, g_woh); cudaGetSymbolAddress((void**)&wol, g_wol);
    cudaGetSymbolAddress((void**)&XFh, g_XFh); cudaGetSymbolAddress((void**)&XFl, g_XFl);
    cudaGetSymbolAddress((void**)&XAh, g_XAh); cudaGetSymbolAddress((void**)&XAl, g_XAl);
    cudaGetSymbolAddress((void**)&HAh, g_HAh); cudaGetSymbolAddress((void**)&HAl, g_HAl);
    cudaGetSymbolAddress((void**)&HBh, g_HBh); cudaGetSymbolAddress((void**)&HBl, g_HBl);

    cudaFuncSetAttribute(mma_gemm<1,1,0>, cudaFuncAttributeMaxDynamicSharedMemorySize, SM_TOTAL);
    cudaFuncSetAttribute(mma_gemm<0,1,1>, cudaFuncAttributeMaxDynamicSharedMemorySize, SM_TOTAL);
    cudaFuncSetAttribute(mma_gemm<1,0,0>, cudaFuncAttributeMaxDynamicSharedMemorySize, SM_TOTAL);

    prep_scale_kernel<<<F_, C_>>>(g);

    {
        int n;
        n = F_ * C_ * C_;              split_kernel<<<(n + 255) / 256, 256>>>(Wp, Wph, Wpl, n);
        n = F_ * COUP_ * D1_;          split_kernel<<<(n + 255) / 256, 256>>>(w0, w0h, w0l, n);
        n = F_ * NBL_ * COUP_ * COUP_; split_kernel<<<(n + 255) / 256, 256>>>(wh, whh, whl, n);
        n = F_ * 2 * D2_ * COUP_;      split_kernel<<<(n + 255) / 256, 256>>>(wo, woh, wol, n);
    }

    // flow-0 input prep (uses g_scale[0:512] computed by prep_scale_kernel)
    prep0_full_kernel<<<(B_ * C_ + 255) / 256, 256>>>(z0, off);

    for (int f = 0; f < F_; f++) {
        float* Xcur = (f & 1) ? X1 : X0;

        const __nv_bfloat16* Wph_f = Wph + (size_t)f * C_ * C_;
        const __nv_bfloat16* Wpl_f = Wpl + (size_t)f * C_ * C_;
        const __nv_bfloat16* w0h_f = w0h + (size_t)f * COUP_ * D1_;
        const __nv_bfloat16* w0l_f = w0l + (size_t)f * COUP_ * D1_;
        const __nv_bfloat16* whh0  = whh + (size_t)f * NBL_ * COUP_ * COUP_;
        const __nv_bfloat16* whl0  = whl + (size_t)f * NBL_ * COUP_ * COUP_;
        const __nv_bfloat16* whh1  = whh0 + (size_t)COUP_ * COUP_;
        const __nv_bfloat16* whl1  = whl0 + (size_t)COUP_ * COUP_;
        const __nv_bfloat16* woh_f = woh + (size_t)f * 2 * D2_ * COUP_;
        const __nv_bfloat16* wol_f = wol + (size_t)f * 2 * D2_ * COUP_;
        const float* b0_f  = b0 + (size_t)f * COUP_;
        const float* bh_f0 = bh + (size_t)f * NBL_ * COUP_;
        const float* bh_f1 = bh_f0 + COUP_;
        const float* bo_f  = bo + (size_t)f * 2 * D2_;

        // 1) X = XF @ Wp^T ; fp32 out + x1 split planes
        mma_gemm<1,1,0><<<dim3(C_ / 128, B_ / 128), 256, SM_TOTAL>>>(
            XFh, XFl, Wph_f, Wpl_f, nullptr,
            Xcur, C_, XAh, XAl, D1_, D1_, C_, 1.0f);

        // 2) H = relu(x1 @ w0^T + b0)
        mma_gemm<0,1,1><<<dim3(COUP_ / 128, B_ / 128), 256, SM_TOTAL>>>(
            XAh, XAl, w0h_f, w0l_f, b0_f,
            nullptr, 0, HAh, HAl, COUP_, COUP_, D1_, 1.0f);

        // 3) H' = relu(H @ wh0^T + bh0)
        mma_gemm<0,1,1><<<dim3(COUP_ / 128, B_ / 128), 256, SM_TOTAL>>>(
            HAh, HAl, whh0, whl0, bh_f0,
            nullptr, 0, HBh, HBl, COUP_, COUP_, COUP_, 1.0f);

        // 4) H = relu(H' @ wh1^T + bh1)
        mma_gemm<0,1,1><<<dim3(COUP_ / 128, B_ / 128), 256, SM_TOTAL>>>(
            HBh, HBl, whh1, whl1, bh_f1,
            nullptr, 0, HAh, HAl, COUP_, COUP_, COUP_, 1.0f);

        // 5) a = 0.1*(H @ wo^T + bo) ; fp32 out
        mma_gemm<1,0,0><<<dim3((2 * D2_) / 128, B_ / 128), 256, SM_TOTAL>>>(
            HAh, HAl, woh_f, wol_f, bo_f,
            Abuf, C_, nullptr, nullptr, 0, 0, COUP_, 0.1f);

        // 6) coupling + log-det + next-flow input prep
        int do_next = (f + 1 < F_) ? 1 : 0;
        const float* sc_n  = scaleP + (size_t)((f + 1) % F_) * C_;
        const float* off_n = off + (size_t)((f + 1) % F_) * C_;
        coupling_kernel<<<B_ / 8, 256>>>(Xcur, f, sc_n, off_n, do_next);
    }

    finalize_kernel<<<(B_ * C_ + B_ + 255) / 256, 256>>>(X1, out);
}